// round 1
// baseline (speedup 1.0000x reference)
#include <cuda_runtime.h>
#include <cuda_bf16.h>
#include <math.h>

#define T_TOK 8192
#define H 1024
#define E 8
#define CAP 1024   // capacity = T/E

// ---------------- scratch (no allocations allowed) ----------------
__device__ int   g_expert_idx[T_TOK];
__device__ float g_gate[T_TOK];
__device__ int   g_slot_token[E * CAP];   // token id per (expert, slot), -1 if empty

// ---------------- kernel 1: routing ----------------
// one warp per token. wg staged in shared (32 KB).
__global__ void route_kernel(const float* __restrict__ x,
                             const float* __restrict__ wg) {
    __shared__ float s_wg[H * E];
    for (int i = threadIdx.x; i < H * E; i += blockDim.x) s_wg[i] = wg[i];
    __syncthreads();

    int warp = (blockIdx.x * blockDim.x + threadIdx.x) >> 5;
    int lane = threadIdx.x & 31;
    if (warp >= T_TOK) return;

    const float* xp = x + (size_t)warp * H;
    float acc[E];
#pragma unroll
    for (int e = 0; e < E; e++) acc[e] = 0.f;

    for (int k = lane; k < H; k += 32) {
        float xv = xp[k];
        const float* w = s_wg + k * E;
#pragma unroll
        for (int e = 0; e < E; e++) acc[e] = fmaf(xv, w[e], acc[e]);
    }
#pragma unroll
    for (int e = 0; e < E; e++) {
#pragma unroll
        for (int o = 16; o > 0; o >>= 1)
            acc[e] += __shfl_down_sync(0xffffffffu, acc[e], o);
    }
    if (lane == 0) {
        float m = acc[0]; int bi = 0;
#pragma unroll
        for (int e = 1; e < E; e++)
            if (acc[e] > m) { m = acc[e]; bi = e; }   // first-max = jnp.argmax
        float s = 0.f;
#pragma unroll
        for (int e = 0; e < E; e++) s += expf(acc[e] - m);
        g_expert_idx[warp] = bi;
        g_gate[warp]       = 1.f / s;   // softmax prob of argmax expert
    }
}

// ---------------- kernel 2: order-preserving scan + capacity ----------------
// single block, 1024 threads, 8 tokens each (in token order).
__global__ void scan_kernel() {
    __shared__ int sc[1024];
    int tid = threadIdx.x;

    // init slot table to empty
    for (int i = tid; i < E * CAP; i += 1024) g_slot_token[i] = -1;

    const int base = tid * 8;
    int eidx[8];
    int cnt[E];
#pragma unroll
    for (int q = 0; q < E; q++) cnt[q] = 0;
#pragma unroll
    for (int j = 0; j < 8; j++) {
        int e = g_expert_idx[base + j];
        eidx[j] = e;
#pragma unroll
        for (int q = 0; q < E; q++) cnt[q] += (e == q);
    }

    int off[E];
#pragma unroll
    for (int e = 0; e < E; e++) {
        sc[tid] = cnt[e];
        __syncthreads();
        // Hillis-Steele inclusive scan
        for (int d = 1; d < 1024; d <<= 1) {
            int v = (tid >= d) ? sc[tid - d] : 0;
            __syncthreads();
            sc[tid] += v;
            __syncthreads();
        }
        off[e] = sc[tid] - cnt[e];   // exclusive prefix for this thread
        __syncthreads();
    }

    // replay tokens in order, assign slots, drop over-capacity
#pragma unroll
    for (int j = 0; j < 8; j++) {
        int t = base + j;
        int e = eidx[j];
        int p = 0;
#pragma unroll
        for (int q = 0; q < E; q++)
            if (e == q) { p = off[q]; off[q] = p + 1; }
        if (p < CAP) g_slot_token[e * CAP + p] = t;
        // dropped tokens: output stays zero (out pre-zeroed)
    }
}

// ---------------- kernel 3: zero output ----------------
__global__ void zero_kernel(float4* __restrict__ out) {
    size_t i = (size_t)blockIdx.x * blockDim.x + threadIdx.x;
    out[i] = make_float4(0.f, 0.f, 0.f, 0.f);
}

// ---------------- kernel 4: grouped GEMM + scatter ----------------
// per expert e: Y[s, f] = sum_h X[token(s), h] * W[e, f, h]
// out[token, f] = gate[token] * (Y[s, f] + b[e, f])
#define BM 64
#define BN 64
#define BK 16
__global__ __launch_bounds__(256) void expert_gemm(
    const float* __restrict__ x, const float* __restrict__ W,
    const float* __restrict__ b, float* __restrict__ out) {
    __shared__ float As[BK][BM + 1];
    __shared__ float Bs[BK][BN + 1];

    const int e  = blockIdx.z;
    const int bm = blockIdx.y * BM;   // slot tile
    const int bn = blockIdx.x * BN;   // out-feature tile
    const int tid = threadIdx.x;
    const int ty = tid >> 4, tx = tid & 15;

    // load mapping: 256 threads, each loads one float4 of A and B per K-step
    const int lrow = tid >> 2;
    const int lk4  = (tid & 3) * 4;

    const int atok = g_slot_token[e * CAP + bm + lrow];
    const float* arow = (atok >= 0) ? (x + (size_t)atok * H) : nullptr;
    const float* brow = W + ((size_t)e * H + (bn + lrow)) * (size_t)H;

    float acc[4][4];
#pragma unroll
    for (int i = 0; i < 4; i++)
#pragma unroll
        for (int j = 0; j < 4; j++) acc[i][j] = 0.f;

    for (int k0 = 0; k0 < H; k0 += BK) {
        float4 av = arow ? *(const float4*)(arow + k0 + lk4)
                         : make_float4(0.f, 0.f, 0.f, 0.f);
        float4 bv = *(const float4*)(brow + k0 + lk4);
        __syncthreads();
        As[lk4 + 0][lrow] = av.x; As[lk4 + 1][lrow] = av.y;
        As[lk4 + 2][lrow] = av.z; As[lk4 + 3][lrow] = av.w;
        Bs[lk4 + 0][lrow] = bv.x; Bs[lk4 + 1][lrow] = bv.y;
        Bs[lk4 + 2][lrow] = bv.z; Bs[lk4 + 3][lrow] = bv.w;
        __syncthreads();
#pragma unroll
        for (int k = 0; k < BK; k++) {
            float a[4], bb[4];
#pragma unroll
            for (int i = 0; i < 4; i++) a[i]  = As[k][ty * 4 + i];
#pragma unroll
            for (int j = 0; j < 4; j++) bb[j] = Bs[k][tx * 4 + j];
#pragma unroll
            for (int i = 0; i < 4; i++)
#pragma unroll
                for (int j = 0; j < 4; j++)
                    acc[i][j] = fmaf(a[i], bb[j], acc[i][j]);
        }
    }

    // epilogue: scatter scaled outputs back to token rows
#pragma unroll
    for (int i = 0; i < 4; i++) {
        int s   = bm + ty * 4 + i;
        int tok = g_slot_token[e * CAP + s];
        if (tok < 0) continue;
        float g = g_gate[tok];
        float*       op = out + (size_t)tok * H + bn + tx * 4;
        const float* bp = b + e * H + bn + tx * 4;
#pragma unroll
        for (int j = 0; j < 4; j++)
            op[j] = g * (acc[i][j] + bp[j]);
    }
}

extern "C" void kernel_launch(void* const* d_in, const int* in_sizes, int n_in,
                              void* d_out, int out_size) {
    const float* x  = (const float*)d_in[0];   // [T, H]
    const float* wg = (const float*)d_in[1];   // [H, E]
    const float* W  = (const float*)d_in[2];   // [E, H, H]
    const float* b  = (const float*)d_in[3];   // [E, H]
    float* out = (float*)d_out;                // [T, H]

    // routing: 8 warps (tokens) per block
    route_kernel<<<T_TOK / 8, 256>>>(x, wg);
    // order-preserving scan + capacity assignment
    scan_kernel<<<1, 1024>>>();
    // zero output (dropped tokens must read back 0)
    zero_kernel<<<(T_TOK * H / 4) / 256, 256>>>((float4*)out);
    // grouped expert GEMM + scatter
    dim3 grid(H / BN, CAP / BM, E);
    expert_gemm<<<grid, 256>>>(x, W, b, out);
}

// round 2
// speedup vs baseline: 1.6012x; 1.6012x over previous
#include <cuda_runtime.h>
#include <cuda_bf16.h>
#include <math.h>

#define T_TOK 8192
#define H 1024
#define E 8
#define CAP 1024   // capacity = T/E

// ---------------- scratch (no allocations allowed) ----------------
__device__ int   g_expert_idx[T_TOK];
__device__ float g_gate[T_TOK];
__device__ int   g_slot_token[E * CAP];   // token id per (expert, slot), -1 if empty

// ---------------- kernel 1: routing ----------------
// one warp per token. wg staged in shared (32 KB).
__global__ void route_kernel(const float* __restrict__ x,
                             const float* __restrict__ wg) {
    __shared__ float s_wg[H * E];
    for (int i = threadIdx.x; i < H * E; i += blockDim.x) s_wg[i] = wg[i];
    __syncthreads();

    int warp = (blockIdx.x * blockDim.x + threadIdx.x) >> 5;
    int lane = threadIdx.x & 31;
    if (warp >= T_TOK) return;

    const float* xp = x + (size_t)warp * H;
    float acc[E];
#pragma unroll
    for (int e = 0; e < E; e++) acc[e] = 0.f;

    for (int k = lane; k < H; k += 32) {
        float xv = xp[k];
        const float* w = s_wg + k * E;
#pragma unroll
        for (int e = 0; e < E; e++) acc[e] = fmaf(xv, w[e], acc[e]);
    }
#pragma unroll
    for (int e = 0; e < E; e++) {
#pragma unroll
        for (int o = 16; o > 0; o >>= 1)
            acc[e] += __shfl_down_sync(0xffffffffu, acc[e], o);
    }
    if (lane == 0) {
        float m = acc[0]; int bi = 0;
#pragma unroll
        for (int e = 1; e < E; e++)
            if (acc[e] > m) { m = acc[e]; bi = e; }   // first-max = jnp.argmax
        float s = 0.f;
#pragma unroll
        for (int e = 0; e < E; e++) s += expf(acc[e] - m);
        g_expert_idx[warp] = bi;
        g_gate[warp]       = 1.f / s;   // softmax prob of argmax expert
    }
}

// ---------------- kernel 2: order-preserving scan + capacity ----------------
// single block, 1024 threads, 8 tokens each (in token order).
// 8 expert counters packed into 2 x uint64 (16 bits each) -> 2 scans.
__global__ void scan_kernel() {
    __shared__ unsigned long long sc0[1024];
    __shared__ unsigned long long sc1[1024];
    int tid = threadIdx.x;

    // init slot table to empty
    for (int i = tid; i < E * CAP; i += 1024) g_slot_token[i] = -1;

    const int base = tid * 8;
    int eidx[8];
    unsigned long long c0 = 0ULL, c1 = 0ULL;
#pragma unroll
    for (int j = 0; j < 8; j++) {
        int e = g_expert_idx[base + j];
        eidx[j] = e;
        if (e < 4) c0 += 1ULL << (16 * e);
        else       c1 += 1ULL << (16 * (e - 4));
    }

    sc0[tid] = c0; sc1[tid] = c1;
    __syncthreads();
    for (int d = 1; d < 1024; d <<= 1) {
        unsigned long long v0 = (tid >= d) ? sc0[tid - d] : 0ULL;
        unsigned long long v1 = (tid >= d) ? sc1[tid - d] : 0ULL;
        __syncthreads();
        sc0[tid] += v0; sc1[tid] += v1;
        __syncthreads();
    }
    unsigned long long o0 = sc0[tid] - c0;   // exclusive prefix (packed)
    unsigned long long o1 = sc1[tid] - c1;

    int off[E];
#pragma unroll
    for (int e = 0; e < 4; e++) {
        off[e]     = (int)((o0 >> (16 * e)) & 0xFFFFULL);
        off[e + 4] = (int)((o1 >> (16 * e)) & 0xFFFFULL);
    }

    // replay tokens in order, assign slots, drop over-capacity
#pragma unroll
    for (int j = 0; j < 8; j++) {
        int t = base + j;
        int e = eidx[j];
        int p = 0;
#pragma unroll
        for (int q = 0; q < E; q++)
            if (e == q) { p = off[q]; off[q] = p + 1; }
        if (p < CAP) g_slot_token[e * CAP + p] = t;
    }
}

// ---------------- kernel 3: zero output ----------------
__global__ void zero_kernel(float4* __restrict__ out) {
    size_t i = (size_t)blockIdx.x * blockDim.x + threadIdx.x;
    out[i] = make_float4(0.f, 0.f, 0.f, 0.f);
}

// ---------------- kernel 4: grouped GEMM + scatter ----------------
// per expert e: Y[s, f] = sum_h X[token(s), h] * W[e, f, h]
// out[token, f] = gate[token] * (Y[s, f] + b[e, f])
// 128x128x8 block tile, 8x8 per thread (split 4+4 rows / 4+4 cols for
// conflict-free LDS.128), double-buffered smem, register prefetch.
#define BM 128
#define BN 128
#define BK 8
__global__ __launch_bounds__(256, 2) void expert_gemm(
    const float* __restrict__ x, const float* __restrict__ W,
    const float* __restrict__ b, float* __restrict__ out) {
    __shared__ float As[2][BK][BM];
    __shared__ float Bs[2][BK][BN];

    const int e  = blockIdx.z;
    const int bm = blockIdx.y * BM;   // slot tile
    const int bn = blockIdx.x * BN;   // out-feature tile
    const int tid = threadIdx.x;
    const int tx = tid & 15;          // col group 0..15
    const int ty = tid >> 4;          // row group 0..15

    // global load mapping: each thread loads one float4 of A and one of B
    const int lrow = tid >> 1;          // 0..127
    const int lk4  = (tid & 1) * 4;     // 0 or 4

    const int atok = g_slot_token[e * CAP + bm + lrow];
    const float* arow = (atok >= 0) ? (x + (size_t)atok * H + lk4) : nullptr;
    const float* brow = W + ((size_t)e * H + (bn + lrow)) * (size_t)H + lk4;

    float acc[8][8];
#pragma unroll
    for (int i = 0; i < 8; i++)
#pragma unroll
        for (int j = 0; j < 8; j++) acc[i][j] = 0.f;

    // prologue: load tile 0
    float4 av = arow ? *(const float4*)(arow) : make_float4(0.f, 0.f, 0.f, 0.f);
    float4 bv = *(const float4*)(brow);
    As[0][lk4 + 0][lrow] = av.x; As[0][lk4 + 1][lrow] = av.y;
    As[0][lk4 + 2][lrow] = av.z; As[0][lk4 + 3][lrow] = av.w;
    Bs[0][lk4 + 0][lrow] = bv.x; Bs[0][lk4 + 1][lrow] = bv.y;
    Bs[0][lk4 + 2][lrow] = bv.z; Bs[0][lk4 + 3][lrow] = bv.w;
    __syncthreads();

    int buf = 0;
    for (int k0 = BK; k0 < H; k0 += BK) {
        // prefetch next tile into registers
        av = arow ? *(const float4*)(arow + k0) : make_float4(0.f, 0.f, 0.f, 0.f);
        bv = *(const float4*)(brow + k0);

        // compute on current buffer
#pragma unroll
        for (int k = 0; k < BK; k++) {
            float4 a0 = *(const float4*)&As[buf][k][ty * 4];
            float4 a1 = *(const float4*)&As[buf][k][64 + ty * 4];
            float4 b0 = *(const float4*)&Bs[buf][k][tx * 4];
            float4 b1 = *(const float4*)&Bs[buf][k][64 + tx * 4];
            float a[8] = {a0.x, a0.y, a0.z, a0.w, a1.x, a1.y, a1.z, a1.w};
            float bb[8] = {b0.x, b0.y, b0.z, b0.w, b1.x, b1.y, b1.z, b1.w};
#pragma unroll
            for (int i = 0; i < 8; i++)
#pragma unroll
                for (int j = 0; j < 8; j++)
                    acc[i][j] = fmaf(a[i], bb[j], acc[i][j]);
        }

        // store prefetched tile into the other buffer
        int nb = buf ^ 1;
        As[nb][lk4 + 0][lrow] = av.x; As[nb][lk4 + 1][lrow] = av.y;
        As[nb][lk4 + 2][lrow] = av.z; As[nb][lk4 + 3][lrow] = av.w;
        Bs[nb][lk4 + 0][lrow] = bv.x; Bs[nb][lk4 + 1][lrow] = bv.y;
        Bs[nb][lk4 + 2][lrow] = bv.z; Bs[nb][lk4 + 3][lrow] = bv.w;
        __syncthreads();
        buf = nb;
    }

    // final tile compute
#pragma unroll
    for (int k = 0; k < BK; k++) {
        float4 a0 = *(const float4*)&As[buf][k][ty * 4];
        float4 a1 = *(const float4*)&As[buf][k][64 + ty * 4];
        float4 b0 = *(const float4*)&Bs[buf][k][tx * 4];
        float4 b1 = *(const float4*)&Bs[buf][k][64 + tx * 4];
        float a[8] = {a0.x, a0.y, a0.z, a0.w, a1.x, a1.y, a1.z, a1.w};
        float bb[8] = {b0.x, b0.y, b0.z, b0.w, b1.x, b1.y, b1.z, b1.w};
#pragma unroll
        for (int i = 0; i < 8; i++)
#pragma unroll
            for (int j = 0; j < 8; j++)
                acc[i][j] = fmaf(a[i], bb[j], acc[i][j]);
    }

    // epilogue: scatter scaled outputs back to token rows
    // rows: bm + {0,64} + ty*4 + i ; cols: bn + {0,64} + tx*4 + j
    const float4 bb0 = *(const float4*)(b + (size_t)e * H + bn + tx * 4);
    const float4 bb1 = *(const float4*)(b + (size_t)e * H + bn + 64 + tx * 4);
#pragma unroll
    for (int half = 0; half < 2; half++) {
#pragma unroll
        for (int i = 0; i < 4; i++) {
            int m = bm + half * 64 + ty * 4 + i;
            int tok = g_slot_token[e * CAP + m];
            if (tok < 0) continue;
            float g = g_gate[tok];
            int r = half * 4 + i;
            float* op = out + (size_t)tok * H + bn;
            float4 v0, v1;
            v0.x = g * (acc[r][0] + bb0.x);
            v0.y = g * (acc[r][1] + bb0.y);
            v0.z = g * (acc[r][2] + bb0.z);
            v0.w = g * (acc[r][3] + bb0.w);
            v1.x = g * (acc[r][4] + bb1.x);
            v1.y = g * (acc[r][5] + bb1.y);
            v1.z = g * (acc[r][6] + bb1.z);
            v1.w = g * (acc[r][7] + bb1.w);
            *(float4*)(op + tx * 4)      = v0;
            *(float4*)(op + 64 + tx * 4) = v1;
        }
    }
}

extern "C" void kernel_launch(void* const* d_in, const int* in_sizes, int n_in,
                              void* d_out, int out_size) {
    const float* x  = (const float*)d_in[0];   // [T, H]
    const float* wg = (const float*)d_in[1];   // [H, E]
    const float* W  = (const float*)d_in[2];   // [E, H, H]
    const float* b  = (const float*)d_in[3];   // [E, H]
    float* out = (float*)d_out;                // [T, H]

    route_kernel<<<T_TOK / 8, 256>>>(x, wg);
    scan_kernel<<<1, 1024>>>();
    zero_kernel<<<(T_TOK * H / 4) / 256, 256>>>((float4*)out);
    dim3 grid(H / BN, CAP / BM, E);
    expert_gemm<<<grid, 256>>>(x, W, b, out);
}

// round 4
// speedup vs baseline: 2.4265x; 1.5154x over previous
#include <cuda_runtime.h>
#include <cuda_bf16.h>
#include <math.h>
#include <stdint.h>

#define T_TOK 8192
#define H 1024
#define E 8
#define CAP 1024   // capacity = T/E

// ---------------- scratch (no allocations allowed) ----------------
__device__ int   g_expert_idx[T_TOK];
__device__ float g_gate[T_TOK];
__device__ int   g_slot_token[E * CAP];   // token id per (expert, slot), -1 if empty

// ---------------- kernel 1: routing ----------------
__global__ void route_kernel(const float* __restrict__ x,
                             const float* __restrict__ wg) {
    __shared__ float s_wg[H * E];
    for (int i = threadIdx.x; i < H * E; i += blockDim.x) s_wg[i] = wg[i];
    __syncthreads();

    int warp = (blockIdx.x * blockDim.x + threadIdx.x) >> 5;
    int lane = threadIdx.x & 31;
    if (warp >= T_TOK) return;

    const float* xp = x + (size_t)warp * H;
    float acc[E];
#pragma unroll
    for (int e = 0; e < E; e++) acc[e] = 0.f;
    for (int k = lane; k < H; k += 32) {
        float xv = xp[k];
        const float* w = s_wg + k * E;
#pragma unroll
        for (int e = 0; e < E; e++) acc[e] = fmaf(xv, w[e], acc[e]);
    }
#pragma unroll
    for (int e = 0; e < E; e++) {
#pragma unroll
        for (int o = 16; o > 0; o >>= 1)
            acc[e] += __shfl_down_sync(0xffffffffu, acc[e], o);
    }
    if (lane == 0) {
        float m = acc[0]; int bi = 0;
#pragma unroll
        for (int e = 1; e < E; e++)
            if (acc[e] > m) { m = acc[e]; bi = e; }
        float s = 0.f;
#pragma unroll
        for (int e = 0; e < E; e++) s += expf(acc[e] - m);
        g_expert_idx[warp] = bi;
        g_gate[warp]       = 1.f / s;
    }
}

// ---------------- kernel 2: order-preserving scan + capacity ----------------
__global__ void scan_kernel() {
    __shared__ unsigned long long sc0[1024];
    __shared__ unsigned long long sc1[1024];
    int tid = threadIdx.x;

    const int base = tid * 8;
    int eidx[8];
    unsigned long long c0 = 0ULL, c1 = 0ULL;
#pragma unroll
    for (int j = 0; j < 8; j++) {
        int e = g_expert_idx[base + j];
        eidx[j] = e;
        if (e < 4) c0 += 1ULL << (16 * e);
        else       c1 += 1ULL << (16 * (e - 4));
    }
    sc0[tid] = c0; sc1[tid] = c1;
    __syncthreads();
    for (int d = 1; d < 1024; d <<= 1) {
        unsigned long long v0 = (tid >= d) ? sc0[tid - d] : 0ULL;
        unsigned long long v1 = (tid >= d) ? sc1[tid - d] : 0ULL;
        __syncthreads();
        sc0[tid] += v0; sc1[tid] += v1;
        __syncthreads();
    }
    unsigned long long o0 = sc0[tid] - c0;
    unsigned long long o1 = sc1[tid] - c1;

    int off[E];
#pragma unroll
    for (int e = 0; e < 4; e++) {
        off[e]     = (int)((o0 >> (16 * e)) & 0xFFFFULL);
        off[e + 4] = (int)((o1 >> (16 * e)) & 0xFFFFULL);
    }
    for (int i = tid; i < E * CAP; i += 1024) g_slot_token[i] = -1;
    __syncthreads();
#pragma unroll
    for (int j = 0; j < 8; j++) {
        int t = base + j;
        int e = eidx[j];
        int p = 0;
#pragma unroll
        for (int q = 0; q < E; q++)
            if (e == q) { p = off[q]; off[q] = p + 1; }
        if (p < CAP) g_slot_token[e * CAP + p] = t;
    }
}

// ---------------- kernel 3: zero output ----------------
__global__ void zero_kernel(float4* __restrict__ out) {
    size_t i = (size_t)blockIdx.x * blockDim.x + threadIdx.x;
    out[i] = make_float4(0.f, 0.f, 0.f, 0.f);
}

// ---------------- GEMM via mma.sync bf16 (3-term hi/lo split) ----------------
#define BM 128
#define BN 128
#define BK 32
#define KITER (H / BK)            // 32
#define LDS_STRIDE 40             // bf16 elems per smem row (32 data + 8 pad) = 80B
#define PLANE_B (BM * LDS_STRIDE * 2)   // 10240 bytes per plane
#define SMEM_TOK 512
#define GEMM_SMEM (SMEM_TOK + 8 * PLANE_B)  // 82432 bytes

__device__ __forceinline__ uint32_t smem_u32(const void* p) {
    uint32_t a;
    asm("{ .reg .u64 t; cvta.to.shared.u64 t, %1; cvt.u32.u64 %0, t; }" : "=r"(a) : "l"(p));
    return a;
}
__device__ __forceinline__ void ldsm4(uint32_t& r0, uint32_t& r1, uint32_t& r2, uint32_t& r3,
                                      uint32_t addr) {
    asm volatile("ldmatrix.sync.aligned.m8n8.x4.shared.b16 {%0,%1,%2,%3}, [%4];"
                 : "=r"(r0), "=r"(r1), "=r"(r2), "=r"(r3) : "r"(addr));
}
__device__ __forceinline__ void mma16816(float* d, const uint32_t* a, uint32_t b0, uint32_t b1) {
    asm volatile("mma.sync.aligned.m16n8k16.row.col.f32.bf16.bf16.f32 "
                 "{%0,%1,%2,%3}, {%4,%5,%6,%7}, {%8,%9}, {%0,%1,%2,%3};"
                 : "+f"(d[0]), "+f"(d[1]), "+f"(d[2]), "+f"(d[3])
                 : "r"(a[0]), "r"(a[1]), "r"(a[2]), "r"(a[3]), "r"(b0), "r"(b1));
}
__device__ __forceinline__ void split4(float4 v, uint2& hi, uint2& lo) {
    __nv_bfloat162 ha = __floats2bfloat162_rn(v.x, v.y);
    __nv_bfloat162 hb = __floats2bfloat162_rn(v.z, v.w);
    __nv_bfloat162 la = __floats2bfloat162_rn(v.x - __low2float(ha), v.y - __high2float(ha));
    __nv_bfloat162 lb = __floats2bfloat162_rn(v.z - __low2float(hb), v.w - __high2float(hb));
    hi.x = *(uint32_t*)&ha; hi.y = *(uint32_t*)&hb;
    lo.x = *(uint32_t*)&la; lo.y = *(uint32_t*)&lb;
}

__global__ void __launch_bounds__(256, 1)
moe_gemm(const float* __restrict__ x, const float* __restrict__ W,
         const float* __restrict__ bias, float* __restrict__ out) {
    extern __shared__ char smem[];
    int* s_tok = (int*)smem;
    char* s_data = smem + SMEM_TOK;
    const uint32_t sbase = smem_u32(smem) + SMEM_TOK;

    const int tid  = threadIdx.x;
    const int lane = tid & 31;
    const int wid  = tid >> 5;
    const int bm = blockIdx.y * BM;       // global slot row base
    const int bn = blockIdx.x * BN;       // output feature base
    const int e  = bm >> 10;              // expert

    if (tid < BM) s_tok[tid] = g_slot_token[bm + tid];
    __syncthreads();

    // ---- per-thread global->smem mapping (fixed across K) ----
    const int seg = tid & 7;              // 16B segment (4 fp32) within 128B row chunk
    int rowi[4];
    const float* aptr[4];
    const float* bptr[4];
    uint32_t stsb[4];                     // byte offset within a plane
#pragma unroll
    for (int i = 0; i < 4; i++) {
        rowi[i] = i * 32 + (tid >> 3);
        int tok = s_tok[rowi[i]];
        aptr[i] = (tok >= 0) ? (x + (size_t)tok * H + seg * 4) : nullptr;
        bptr[i] = W + ((size_t)e * H + bn + rowi[i]) * (size_t)H + seg * 4;
        stsb[i] = (uint32_t)(rowi[i] * (LDS_STRIDE * 2) + seg * 8);
    }

    float D[4][4][4];
#pragma unroll
    for (int mt = 0; mt < 4; mt++)
#pragma unroll
        for (int nt = 0; nt < 4; nt++)
#pragma unroll
            for (int r = 0; r < 4; r++) D[mt][nt][r] = 0.f;

    const int mrow = (wid >> 2) * 64 + (lane & 15);
    const int nrow = (wid & 3) * 32 + (lane & 15);

    float4 pa[4], pb[4];
    // prologue: load chunk 0
#pragma unroll
    for (int i = 0; i < 4; i++) {
        pa[i] = aptr[i] ? *(const float4*)(aptr[i]) : make_float4(0.f, 0.f, 0.f, 0.f);
        pb[i] = *(const float4*)(bptr[i]);
    }
    // stage chunk 0 into buf 0
    {
        char* bp = s_data;   // buf 0
#pragma unroll
        for (int i = 0; i < 4; i++) {
            uint2 hi, lo;
            split4(pa[i], hi, lo);
            *(uint2*)(bp + stsb[i])               = hi;   // A hi (plane 0)
            *(uint2*)(bp + PLANE_B + stsb[i])     = lo;   // A lo (plane 1)
            split4(pb[i], hi, lo);
            *(uint2*)(bp + 2 * PLANE_B + stsb[i]) = hi;   // B hi (plane 2)
            *(uint2*)(bp + 3 * PLANE_B + stsb[i]) = lo;   // B lo (plane 3)
        }
    }
    __syncthreads();

    for (int kc = 1; kc < KITER; kc++) {
        // prefetch chunk kc
#pragma unroll
        for (int i = 0; i < 4; i++) {
            pa[i] = aptr[i] ? *(const float4*)(aptr[i] + kc * BK)
                            : make_float4(0.f, 0.f, 0.f, 0.f);
            pb[i] = *(const float4*)(bptr[i] + kc * BK);
        }

        // compute chunk kc-1 (buf (kc-1)&1)
        {
            const uint32_t ab = sbase + ((kc - 1) & 1) * 4 * PLANE_B;
#pragma unroll
            for (int ks = 0; ks < 2; ks++) {
                const uint32_t colb = (uint32_t)((ks * 16 + (lane >> 4) * 8) * 2);
                uint32_t ahi[4][4], alo[4][4], bh[2][4], bl[2][4];
#pragma unroll
                for (int mt = 0; mt < 4; mt++) {
                    uint32_t ad = ab + (mrow + mt * 16) * (LDS_STRIDE * 2) + colb;
                    ldsm4(ahi[mt][0], ahi[mt][1], ahi[mt][2], ahi[mt][3], ad);
                    ldsm4(alo[mt][0], alo[mt][1], alo[mt][2], alo[mt][3], ad + PLANE_B);
                }
#pragma unroll
                for (int np = 0; np < 2; np++) {
                    uint32_t bd = ab + 2 * PLANE_B + (nrow + np * 16) * (LDS_STRIDE * 2) + colb;
                    ldsm4(bh[np][0], bh[np][1], bh[np][2], bh[np][3], bd);
                    ldsm4(bl[np][0], bl[np][1], bl[np][2], bl[np][3], bd + PLANE_B);
                }
#pragma unroll
                for (int mt = 0; mt < 4; mt++)
#pragma unroll
                    for (int nt = 0; nt < 4; nt++) {
                        int np = nt >> 1, od = nt & 1;
                        mma16816(D[mt][nt], ahi[mt], bh[np][od], bh[np][2 + od]);
                        mma16816(D[mt][nt], ahi[mt], bl[np][od], bl[np][2 + od]);
                        mma16816(D[mt][nt], alo[mt], bh[np][od], bh[np][2 + od]);
                    }
            }
        }

        // stage chunk kc into buf kc&1
        {
            char* bp = s_data + (kc & 1) * 4 * PLANE_B;
#pragma unroll
            for (int i = 0; i < 4; i++) {
                uint2 hi, lo;
                split4(pa[i], hi, lo);
                *(uint2*)(bp + stsb[i])               = hi;
                *(uint2*)(bp + PLANE_B + stsb[i])     = lo;
                split4(pb[i], hi, lo);
                *(uint2*)(bp + 2 * PLANE_B + stsb[i]) = hi;
                *(uint2*)(bp + 3 * PLANE_B + stsb[i]) = lo;
            }
        }
        __syncthreads();
    }

    // final chunk compute (buf (KITER-1)&1 = 1)
    {
        const uint32_t ab = sbase + ((KITER - 1) & 1) * 4 * PLANE_B;
#pragma unroll
        for (int ks = 0; ks < 2; ks++) {
            const uint32_t colb = (uint32_t)((ks * 16 + (lane >> 4) * 8) * 2);
            uint32_t ahi[4][4], alo[4][4], bh[2][4], bl[2][4];
#pragma unroll
            for (int mt = 0; mt < 4; mt++) {
                uint32_t ad = ab + (mrow + mt * 16) * (LDS_STRIDE * 2) + colb;
                ldsm4(ahi[mt][0], ahi[mt][1], ahi[mt][2], ahi[mt][3], ad);
                ldsm4(alo[mt][0], alo[mt][1], alo[mt][2], alo[mt][3], ad + PLANE_B);
            }
#pragma unroll
            for (int np = 0; np < 2; np++) {
                uint32_t bd = ab + 2 * PLANE_B + (nrow + np * 16) * (LDS_STRIDE * 2) + colb;
                ldsm4(bh[np][0], bh[np][1], bh[np][2], bh[np][3], bd);
                ldsm4(bl[np][0], bl[np][1], bl[np][2], bl[np][3], bd + PLANE_B);
            }
#pragma unroll
            for (int mt = 0; mt < 4; mt++)
#pragma unroll
                for (int nt = 0; nt < 4; nt++) {
                    int np = nt >> 1, od = nt & 1;
                    mma16816(D[mt][nt], ahi[mt], bh[np][od], bh[np][2 + od]);
                    mma16816(D[mt][nt], ahi[mt], bl[np][od], bl[np][2 + od]);
                    mma16816(D[mt][nt], alo[mt], bh[np][od], bh[np][2 + od]);
                }
        }
    }

    // ---- epilogue: gate * (D + bias) scattered to token rows ----
    const int wm = (wid >> 2) * 64;
    const int wn = (wid & 3) * 32;
#pragma unroll
    for (int mt = 0; mt < 4; mt++) {
#pragma unroll
        for (int half = 0; half < 2; half++) {
            int r = wm + mt * 16 + (lane >> 2) + half * 8;
            int tok = s_tok[r];
            if (tok < 0) continue;
            float g = g_gate[tok];
            float* orow = out + (size_t)tok * H + bn + wn;
#pragma unroll
            for (int nt = 0; nt < 4; nt++) {
                int c = nt * 8 + (lane & 3) * 2;
                float2 bb = *(const float2*)(bias + (size_t)e * H + bn + wn + c);
                float2 v;
                v.x = g * (D[mt][nt][half * 2 + 0] + bb.x);
                v.y = g * (D[mt][nt][half * 2 + 1] + bb.y);
                *(float2*)(orow + c) = v;
            }
        }
    }
}

extern "C" void kernel_launch(void* const* d_in, const int* in_sizes, int n_in,
                              void* d_out, int out_size) {
    const float* x  = (const float*)d_in[0];   // [T, H]
    const float* wg = (const float*)d_in[1];   // [H, E]
    const float* W  = (const float*)d_in[2];   // [E, H, H]
    const float* b  = (const float*)d_in[3];   // [E, H]
    float* out = (float*)d_out;                // [T, H]

    cudaFuncSetAttribute(moe_gemm, cudaFuncAttributeMaxDynamicSharedMemorySize, GEMM_SMEM);

    route_kernel<<<T_TOK / 8, 256>>>(x, wg);
    scan_kernel<<<1, 1024>>>();
    zero_kernel<<<(T_TOK * H / 4) / 256, 256>>>((float4*)out);
    dim3 grid(H / BN, T_TOK / BM);             // (8, 64)
    moe_gemm<<<grid, 256, GEMM_SMEM>>>(x, W, b, out);
}